// round 4
// baseline (speedup 1.0000x reference)
#include <cuda_runtime.h>
#include <math.h>

// Shape-specialized: H=1024, N_HALF=32, L=4096, CHANNELS=1
#define HH    1024
#define NH    32
#define LL    4096
#define TPB   128
#define CHUNK (LL / TPB)     // 32: thread t owns l = t + 128*j
#define NPAIR (NH / 2)       // 16 packed n-pairs

// K[h,l] = 2*Re( sum_n Ceff[h,n] * dA[h,n]^l ),  l = t + 128*j
//        = 2*sum_n ( vr_n * c_{n,j} + vi_n * d_{n,j} )
// with v_n = Ceff_n * dA_n^t (per-thread), c = Re(W^j), d = -Im(W^j),
// W = dA^128 (block-uniform -> SMEM coefficient table).
// Two n per 64-bit f32x2 register: 2 FFMA2 per (pair, j), zero recurrence state.

typedef unsigned long long u64;

__device__ __forceinline__ u64 pk2(float lo, float hi) {
    u64 r; asm("mov.b64 %0, {%1,%2};" : "=l"(r) : "f"(lo), "f"(hi)); return r;
}
__device__ __forceinline__ void upk2(float& lo, float& hi, u64 v) {
    asm("mov.b64 {%0,%1}, %2;" : "=f"(lo), "=f"(hi) : "l"(v));
}
__device__ __forceinline__ u64 fma2(u64 a, u64 b, u64 c) {
    u64 r; asm("fma.rn.f32x2 %0, %1, %2, %3;" : "=l"(r) : "l"(a), "l"(b), "l"(c)); return r;
}

__global__ void __launch_bounds__(TPB, 6)
sskernel_diag(const float* __restrict__ log_dt,
              const float* __restrict__ B_ri,
              const float* __restrict__ C_ri,
              const float* __restrict__ inv_A_real,
              const float* __restrict__ A_imag,
              float* __restrict__ out)
{
    __shared__ float s_lg[NH], s_th[NH];         // log|dA|, arg(dA)
    __shared__ float s_cr[NH], s_ci[NH];         // Ceff
    __shared__ float s_wr[NH], s_wi[NH];         // W = dA^128 (fp64->fp32 of exact)
    __shared__ double s_dwr[NH], s_dwi[NH];      // W in fp64 for coefficient gen
    // Coefficient table: per (pair p, j): {c_lo, c_hi, d_lo, d_hi} = 16B
    __shared__ ulonglong2 s_cd[NPAIR * CHUNK];   // 8 KB

    const int h = blockIdx.x;
    const int t = threadIdx.x;

    // ---- per-(h,n) setup in fp64 (threads 0..31) ----
    if (t < NH) {
        const int n  = t;
        const int hn = h * NH + n;
        double dt = exp((double)log_dt[h]);
        double Ar = -exp((double)inv_A_real[hn]);
        double Ai = (double)A_imag[hn];
        double zr = Ar * dt, zi = Ai * dt;                 // dtA
        double dr = 1.0 - 0.5 * zr, di = -0.5 * zi;        // 1 - dtA/2
        double d2 = dr * dr + di * di;
        double idr =  dr / d2, idi = -di / d2;             // 1/(1-dtA/2)
        double nr = 1.0 + 0.5 * zr, ni = 0.5 * zi;         // 1 + dtA/2
        double dAr = nr * idr - ni * idi;                  // bilinear dA
        double dAi = nr * idi + ni * idr;
        double Br = (double)B_ri[2 * hn],  Bi = (double)B_ri[2 * hn + 1];
        double Cr = (double)C_ri[2 * hn],  Ci = (double)C_ri[2 * hn + 1];
        double bcr = Br * Cr - Bi * Ci,    bci = Br * Ci + Bi * Cr;
        s_cr[n] = (float)((bcr * idr - bci * idi) * dt);   // Ceff
        s_ci[n] = (float)((bcr * idi + bci * idr) * dt);
        s_lg[n] = (float)(0.5 * log(dAr * dAr + dAi * dAi));
        s_th[n] = (float)atan2(dAi, dAr);
        // W = dA^128 via 7 complex squarings (fp64)
        double wr = dAr, wi = dAi;
        #pragma unroll
        for (int s = 0; s < 7; s++) {
            double tr = wr * wr - wi * wi;
            double ti = 2.0 * wr * wi;
            wr = tr; wi = ti;
        }
        s_dwr[n] = wr; s_dwi[n] = wi;
        s_wr[n] = (float)wr; s_wi[n] = (float)wi;
    }
    __syncthreads();

    // ---- coefficient table: c_{n,j} = Re(W^j), d_{n,j} = -Im(W^j) ----
    // 128 threads: n = t&31, warp g = t>>5 handles j in [8g, 8g+8).
    {
        const int n = t & 31, g = t >> 5;
        const double wr = s_dwr[n], wi = s_dwi[n];
        // W^8
        double w2r = wr * wr - wi * wi,   w2i = 2.0 * wr * wi;
        double w4r = w2r * w2r - w2i * w2i, w4i = 2.0 * w2r * w2i;
        double w8r = w4r * w4r - w4i * w4i, w8i = 2.0 * w4r * w4i;
        // B = W^(8g)   (g uniform per warp -> no divergence)
        double br = 1.0, bi = 0.0;
        for (int k = 0; k < g; k++) {
            double tr = br * w8r - bi * w8i;
            bi = br * w8i + bi * w8r; br = tr;
        }
        float* f = (float*)s_cd;
        #pragma unroll
        for (int jj = 0; jj < 8; jj++) {
            const int j = g * 8 + jj;
            const int idx = (((n >> 1) * CHUNK) + j) * 4 + (n & 1);
            f[idx]     = (float)br;       // c
            f[idx + 2] = (float)(-bi);    // d
            double tr = br * wr - bi * wi;
            bi = br * wi + bi * wr; br = tr;
        }
    }
    __syncthreads();

    // ---- main: acc[j] += vr*c + vi*d, packed 2 n per register ----
    u64 acc[CHUNK];
    #pragma unroll
    for (int j = 0; j < CHUNK; j++) acc[j] = 0ull;

    const float l0 = (float)t;

    for (int p = 0; p < NPAIR; p++) {
        float vr[2], vi[2];
        #pragma unroll
        for (int k = 0; k < 2; k++) {
            const int n = 2 * p + k;
            const float cr = s_cr[n], ci = s_ci[n];
            float e = __expf(l0 * s_lg[n]);
            float sn, cs;
            __sincosf(l0 * s_th[n], &sn, &cs);
            vr[k] = e * (cr * cs - ci * sn);
            vi[k] = e * (ci * cs + cr * sn);
        }
        const u64 Vr = pk2(vr[0], vr[1]);
        const u64 Vi = pk2(vi[0], vi[1]);

        const ulonglong2* cd = &s_cd[p * CHUNK];
        #pragma unroll
        for (int j = 0; j < CHUNK; j++) {
            ulonglong2 q = cd[j];                       // broadcast LDS.128
            acc[j] = fma2(Vr, q.x, fma2(Vi, q.y, acc[j]));
        }
    }

    // ---- coalesced stores ----
    float* o = out + (size_t)h * LL + t;
    #pragma unroll
    for (int j = 0; j < CHUNK; j++) {
        float lo, hi;
        upk2(lo, hi, acc[j]);
        o[j * TPB] = 2.0f * (lo + hi);
    }
}

extern "C" void kernel_launch(void* const* d_in, const int* in_sizes, int n_in,
                              void* d_out, int out_size)
{
    const float* log_dt     = (const float*)d_in[0];   // (H,)
    const float* B_ri       = (const float*)d_in[1];   // (H, N, 2)
    const float* C_ri       = (const float*)d_in[2];   // (1, H, N, 2)
    const float* inv_A_real = (const float*)d_in[3];   // (H, N)
    const float* A_imag     = (const float*)d_in[4];   // (H, N)
    float* out = (float*)d_out;                        // (1, H, L)

    sskernel_diag<<<HH, TPB>>>(log_dt, B_ri, C_ri, inv_A_real, A_imag, out);
}

// round 6
// speedup vs baseline: 1.6597x; 1.6597x over previous
#include <cuda_runtime.h>
#include <math.h>

// Shape-specialized: H=1024, N_HALF=32, L=4096, CHANNELS=1
#define HH    1024
#define NH    32
#define TPB   128
#define LL    4096
#define CHUNK 32            // j per thread: l = t + 128*j
#define NPAIR 16            // packed n-pairs
#define NT    4             // j-tiles of 8 per thread

// l = t + 128*(8*jt + r),  W = dA^128.
// x = Re( v * W^{8jt} * W^r ) = Vr[jt]*c_r + Vi[jt]*d_r,
// c_r = Re(W^r), d_r = -Im(W^r)  (block-uniform, SMEM, 1 LDS.128 per (pair,r)
// feeding 8 independent FFMA2). V[jt] register-resident per pair.

typedef unsigned long long u64;

__device__ __forceinline__ u64 pk2(float lo, float hi) {
    u64 r; asm("mov.b64 %0, {%1,%2};" : "=l"(r) : "f"(lo), "f"(hi)); return r;
}
__device__ __forceinline__ void upk2(float& lo, float& hi, u64 v) {
    asm("mov.b64 {%0,%1}, %2;" : "=f"(lo), "=f"(hi) : "l"(v));
}
__device__ __forceinline__ u64 mul2(u64 a, u64 b) {
    u64 r; asm("mul.rn.f32x2 %0, %1, %2;" : "=l"(r) : "l"(a), "l"(b)); return r;
}
__device__ __forceinline__ u64 fma2(u64 a, u64 b, u64 c) {
    u64 r; asm("fma.rn.f32x2 %0, %1, %2, %3;" : "=l"(r) : "l"(a), "l"(b), "l"(c)); return r;
}
__device__ __forceinline__ u64 add2(u64 a, u64 b) {
    u64 r; asm("add.rn.f32x2 %0, %1, %2;" : "=l"(r) : "l"(a), "l"(b)); return r;
}

__global__ void __launch_bounds__(TPB, 4)
sskernel_diag(const float* __restrict__ log_dt,
              const float* __restrict__ B_ri,
              const float* __restrict__ C_ri,
              const float* __restrict__ inv_A_real,
              const float* __restrict__ A_imag,
              float* __restrict__ out)
{
    __shared__ float s_lg[NH], s_th[NH];       // log|dA|, arg(dA)
    __shared__ float s_cr[NH], s_ci[NH];       // 2*Ceff (output 2x folded in)
    // Per pair p: entry 0 = {Re(W^8), -Im(W^8)} packed; entries r=1..7 =
    // {c_r lo, c_r hi, d_r lo, d_r hi}.  2 KB total.
    __shared__ ulonglong2 s_tab[NPAIR][8];
    __shared__ u64 s_w8b[NPAIR];               // +Im(W^8) packed

    const int h = blockIdx.x;
    const int t = threadIdx.x;

    // ---- per-(h,n) setup in fp64 (threads 0..31, one n each) ----
    if (t < NH) {
        const int n  = t;
        const int hn = h * NH + n;
        const int p  = n >> 1, lane = n & 1;
        double dt = exp((double)log_dt[h]);
        double Ar = -exp((double)inv_A_real[hn]);
        double Ai = (double)A_imag[hn];
        double zr = Ar * dt, zi = Ai * dt;                 // dtA
        double dr = 1.0 - 0.5 * zr, di = -0.5 * zi;        // 1 - dtA/2
        double d2 = dr * dr + di * di;
        double idr =  dr / d2, idi = -di / d2;             // 1/(1-dtA/2)
        double nr = 1.0 + 0.5 * zr, ni = 0.5 * zi;         // 1 + dtA/2
        double dAr = nr * idr - ni * idi;                  // bilinear dA
        double dAi = nr * idi + ni * idr;
        double Br = (double)B_ri[2 * hn],  Bi = (double)B_ri[2 * hn + 1];
        double Cr = (double)C_ri[2 * hn],  Ci = (double)C_ri[2 * hn + 1];
        double bcr = Br * Cr - Bi * Ci,    bci = Br * Ci + Bi * Cr;
        s_cr[n] = (float)(2.0 * (bcr * idr - bci * idi) * dt);   // 2*Ceff
        s_ci[n] = (float)(2.0 * (bcr * idi + bci * idr) * dt);
        s_lg[n] = (float)(0.5 * log(dAr * dAr + dAi * dAi));
        s_th[n] = (float)atan2(dAi, dAr);
        // W = dA^128 via 7 complex squarings (fp64)
        double wr = dAr, wi = dAi;
        #pragma unroll
        for (int s = 0; s < 7; s++) {
            double tr = wr * wr - wi * wi;
            double ti = 2.0 * wr * wi;
            wr = tr; wi = ti;
        }
        // powers W^1..W^7, then W^8
        float* tf = (float*)s_tab;
        double cr_ = wr, ci_ = wi;
        #pragma unroll
        for (int r = 1; r < 8; r++) {
            const int base = (p * 8 + r) * 4;
            tf[base + lane]     = (float)cr_;        // c_r
            tf[base + 2 + lane] = (float)(-ci_);     // d_r
            double tr = cr_ * wr - ci_ * wi;
            ci_ = cr_ * wi + ci_ * wr; cr_ = tr;
        }
        // entry 0: W^8 as {a, -b}; +b in side table
        tf[(p * 8) * 4 + lane]     = (float)cr_;
        tf[(p * 8) * 4 + 2 + lane] = (float)(-ci_);
        ((float*)s_w8b)[p * 2 + lane] = (float)ci_;
    }
    __syncthreads();

    // ---- main ----
    u64 acc[CHUNK];
    #pragma unroll
    for (int j = 0; j < CHUNK; j++) acc[j] = 0ull;

    const float l0 = (float)t;

    for (int p = 0; p < NPAIR; p++) {
        // v_n = 2*Ceff_n * dA_n^t for the two n of this pair (MUFU path)
        float vr[2], vi[2];
        #pragma unroll
        for (int k = 0; k < 2; k++) {
            const int n = 2 * p + k;
            const float cr = s_cr[n], ci = s_ci[n];
            float e = __expf(l0 * s_lg[n]);
            float sn, cs;
            __sincosf(l0 * s_th[n], &sn, &cs);
            vr[k] = e * (cr * cs - ci * sn);
            vi[k] = e * (ci * cs + cr * sn);
        }

        const ulonglong2* tp = &s_tab[p][0];
        const ulonglong2 e0 = tp[0];
        const u64 A  = e0.x;           // Re(W^8)
        const u64 NB = e0.y;           // -Im(W^8)
        const u64 Bq = s_w8b[p];       // +Im(W^8)

        // Tile states V[jt] = v * W^{8jt}, jt = 0..3 (12 packed ops)
        u64 Vr[NT], Vi[NT];
        Vr[0] = pk2(vr[0], vr[1]);
        Vi[0] = pk2(vi[0], vi[1]);
        #pragma unroll
        for (int jt = 1; jt < NT; jt++) {
            Vr[jt] = fma2(Vi[jt - 1], NB, mul2(Vr[jt - 1], A));
            Vi[jt] = fma2(Vi[jt - 1], A,  mul2(Vr[jt - 1], Bq));
        }

        // r = 0: x = Vr[jt]
        #pragma unroll
        for (int jt = 0; jt < NT; jt++)
            acc[jt * 8] = add2(acc[jt * 8], Vr[jt]);

        // r = 1..7: one LDS.128 -> 8 independent FFMA2
        #pragma unroll
        for (int r = 1; r < 8; r++) {
            const ulonglong2 q = tp[r];      // (c_r, d_r)
            #pragma unroll
            for (int jt = 0; jt < NT; jt++) {
                const int j = jt * 8 + r;
                acc[j] = fma2(Vr[jt], q.x, fma2(Vi[jt], q.y, acc[j]));
            }
        }
    }

    // ---- coalesced stores (2x already folded into Ceff) ----
    float* o = out + (size_t)h * LL + t;
    #pragma unroll
    for (int j = 0; j < CHUNK; j++) {
        float lo, hi;
        upk2(lo, hi, acc[j]);
        o[j * TPB] = lo + hi;
    }
}

extern "C" void kernel_launch(void* const* d_in, const int* in_sizes, int n_in,
                              void* d_out, int out_size)
{
    const float* log_dt     = (const float*)d_in[0];   // (H,)
    const float* B_ri       = (const float*)d_in[1];   // (H, N, 2)
    const float* C_ri       = (const float*)d_in[2];   // (1, H, N, 2)
    const float* inv_A_real = (const float*)d_in[3];   // (H, N)
    const float* A_imag     = (const float*)d_in[4];   // (H, N)
    float* out = (float*)d_out;                        // (1, H, L)

    sskernel_diag<<<HH, TPB>>>(log_dt, B_ri, C_ri, inv_A_real, A_imag, out);
}